// round 1
// baseline (speedup 1.0000x reference)
#include <cuda_runtime.h>
#include <cuda_bf16.h>
#include <math.h>

#define Bb   64
#define Tt   200
#define Dd   128
#define Mm   50
#define BT   (Bb*Tt)          // 12800
#define NUMQ 1000

// ---------------- scratch (no allocs allowed) ----------------
__device__ float g_k[BT*Dd];        // k embeddings (needed for f)
__device__ float g_w[BT*Mm];        // softmax weights
__device__ float g_e[BT*Dd];        // erase gate
__device__ float g_a[BT*Dd];        // add vector
__device__ float g_read[BT*Dd];     // read vectors
__device__ float g_Mkt[Dd*64];      // Mk^T   [d][m] (padded to 64)
__device__ float g_eWt[Dd*Dd];      // e_W^T  [d][o]
__device__ float g_aWt[Dd*Dd];      // a_W^T  [d][o]
__device__ float g_fWt[2*Dd*Dd];    // f_W^T  [d(256)][o(128)]

__device__ __forceinline__ float sigmoidf_(float x){ return 1.f/(1.f+expf(-x)); }

// ---------------- K0: transpose weights once per call ----------------
__global__ void k0_transpose(const float* __restrict__ Mk, const float* __restrict__ eW,
                             const float* __restrict__ aW, const float* __restrict__ fW){
    int tid = blockIdx.x*blockDim.x + threadIdx.x;
    int nt  = gridDim.x*blockDim.x;
    for (int i=tid; i<Mm*Dd; i+=nt){ int m=i/Dd, d=i%Dd; g_Mkt[d*64+m]=Mk[i]; }
    for (int i=tid; i<Dd*Dd; i+=nt){ int o=i/Dd, d=i%Dd; g_eWt[d*Dd+o]=eW[i]; g_aWt[d*Dd+o]=aW[i]; }
    for (int i=tid; i<Dd*2*Dd; i+=nt){ int o=i/(2*Dd), d=i%(2*Dd); g_fWt[d*Dd+o]=fW[i]; }
}

// ---------------- K1: gather k/v, compute w (softmax), e, a ----------------
// 4 rows (b,t pairs) per 128-thread block. Thread-per-output-column GEMVs
// with transposed weights (coalesced LDG, smem-broadcast activations).
__global__ __launch_bounds__(128) void k1_gates(
    const int* __restrict__ q, const int* __restrict__ r, const int* __restrict__ pid,
    const float* __restrict__ pid_emb, const float* __restrict__ k_emb,
    const float* __restrict__ v_emb,
    const float* __restrict__ e_b, const float* __restrict__ a_b)
{
    const int tid  = threadIdx.x;
    const int lane = tid & 31;
    const int wid  = tid >> 5;
    const int row0 = blockIdx.x * 4;

    __shared__ float k_s[4][Dd];
    __shared__ float v_s[4][Dd];
    __shared__ float wl[4][52];

    #pragma unroll
    for (int rr=0; rr<4; rr++){
        int row = row0 + rr;
        int qi = q[row], ri = r[row], pi = pid[row];
        float pe = pid_emb[pi*Dd + tid];
        float kk = k_emb[qi*Dd + tid] + pe;
        float vv = v_emb[(qi + ri*NUMQ)*Dd + tid] + pe;
        k_s[rr][tid] = kk;
        v_s[rr][tid] = vv;
        g_k[row*Dd + tid] = kk;
    }
    __syncthreads();

    // ---- w logits: thread = memory slot m (m < 50) ----
    if (tid < Mm){
        float a0=0.f,a1=0.f,a2=0.f,a3=0.f;
        #pragma unroll 4
        for (int d=0; d<Dd; d++){
            float mk = g_Mkt[d*64 + tid];
            a0 = fmaf(mk, k_s[0][d], a0);
            a1 = fmaf(mk, k_s[1][d], a1);
            a2 = fmaf(mk, k_s[2][d], a2);
            a3 = fmaf(mk, k_s[3][d], a3);
        }
        wl[0][tid]=a0; wl[1][tid]=a1; wl[2][tid]=a2; wl[3][tid]=a3;
    }
    __syncthreads();

    // ---- softmax over m: warp wid handles row wid ----
    {
        float l0 = (lane      < Mm) ? wl[wid][lane]      : -1e30f;
        float l1 = (lane + 32 < Mm) ? wl[wid][lane + 32] : -1e30f;
        float mx = fmaxf(l0, l1);
        #pragma unroll
        for (int o=16; o; o>>=1) mx = fmaxf(mx, __shfl_xor_sync(0xffffffffu, mx, o));
        float e0 = (lane      < Mm) ? expf(l0 - mx) : 0.f;
        float e1 = (lane + 32 < Mm) ? expf(l1 - mx) : 0.f;
        float s = e0 + e1;
        #pragma unroll
        for (int o=16; o; o>>=1) s += __shfl_xor_sync(0xffffffffu, s, o);
        float inv = 1.f / s;
        int row = row0 + wid;
        if (lane      < Mm) g_w[row*Mm + lane]      = e0 * inv;
        if (lane + 32 < Mm) g_w[row*Mm + lane + 32] = e1 * inv;
    }

    // ---- e / a: thread = output channel o ----
    {
        float ae0=0.f,ae1=0.f,ae2=0.f,ae3=0.f;
        float aa0=0.f,aa1=0.f,aa2=0.f,aa3=0.f;
        #pragma unroll 4
        for (int d=0; d<Dd; d++){
            float ew = g_eWt[d*Dd + tid];
            float aw = g_aWt[d*Dd + tid];
            float v0=v_s[0][d], v1=v_s[1][d], v2=v_s[2][d], v3=v_s[3][d];
            ae0=fmaf(ew,v0,ae0); ae1=fmaf(ew,v1,ae1); ae2=fmaf(ew,v2,ae2); ae3=fmaf(ew,v3,ae3);
            aa0=fmaf(aw,v0,aa0); aa1=fmaf(aw,v1,aa1); aa2=fmaf(aw,v2,aa2); aa3=fmaf(aw,v3,aa3);
        }
        float eb = e_b[tid], ab = a_b[tid];
        g_e[(row0+0)*Dd + tid] = sigmoidf_(ae0 + eb);
        g_e[(row0+1)*Dd + tid] = sigmoidf_(ae1 + eb);
        g_e[(row0+2)*Dd + tid] = sigmoidf_(ae2 + eb);
        g_e[(row0+3)*Dd + tid] = sigmoidf_(ae3 + eb);
        g_a[(row0+0)*Dd + tid] = tanhf(aa0 + ab);
        g_a[(row0+1)*Dd + tid] = tanhf(aa1 + ab);
        g_a[(row0+2)*Dd + tid] = tanhf(aa2 + ab);
        g_a[(row0+3)*Dd + tid] = tanhf(aa3 + ab);
    }
}

// ---------------- K2: sequential scan over T, parallel over (b, d-chunk) ----------------
// grid (4, 64): blockIdx.x = d-chunk of 32, blockIdx.y = batch. 256 threads:
// lane = d within chunk, warp wg owns m in {wg, wg+8, ...}. Mv lives in registers.
__global__ __launch_bounds__(256) void k2_scan(const float* __restrict__ Mv0,
                                               float* __restrict__ out_Mv)
{
    const int b    = blockIdx.y;
    const int lane = threadIdx.x & 31;
    const int wg   = threadIdx.x >> 5;          // 0..7
    const int d    = blockIdx.x * 32 + lane;    // 0..127

    float mv[7];
    #pragma unroll
    for (int i=0; i<7; i++){
        int m = wg + 8*i;
        mv[i] = (m < Mm) ? Mv0[m*Dd + d] : 0.f;
    }

    __shared__ float part[2][8][32];

    const float* wb = g_w + (size_t)b*Tt*Mm;
    const float* eb = g_e + (size_t)b*Tt*Dd;
    const float* ab = g_a + (size_t)b*Tt*Dd;
    float*       rb = g_read + (size_t)b*Tt*Dd;

    // preload t = 0
    float e_d = eb[d];
    float a_d = ab[d];
    float wv[7];
    #pragma unroll
    for (int i=0; i<7; i++){
        int m = wg + 8*i;
        wv[i] = (m < Mm) ? wb[m] : 0.f;
    }

    for (int t=0; t<Tt; t++){
        // prefetch next step (hide L2 latency behind this step's work)
        float e_n = 0.f, a_n = 0.f, wn[7];
        if (t+1 < Tt){
            e_n = eb[(t+1)*Dd + d];
            a_n = ab[(t+1)*Dd + d];
            #pragma unroll
            for (int i=0; i<7; i++){
                int m = wg + 8*i;
                wn[i] = (m < Mm) ? wb[(t+1)*Mm + m] : 0.f;
            }
        } else {
            #pragma unroll
            for (int i=0; i<7; i++) wn[i] = 0.f;
        }

        // read partial: sum over this warp's m's
        float pr = 0.f;
        #pragma unroll
        for (int i=0; i<7; i++){
            int m = wg + 8*i;
            if (m < Mm) pr = fmaf(wv[i], mv[i], pr);
        }
        part[t & 1][wg][lane] = pr;
        __syncthreads();

        if (wg == 0){
            float rs = 0.f;
            #pragma unroll
            for (int j=0; j<8; j++) rs += part[t & 1][j][lane];
            rb[t*Dd + d] = rs;
        }

        // store pre-update state at time index t, then apply rank-1 update
        float* outp = out_Mv + ((size_t)(b*(Tt+1) + t) * Mm) * Dd;
        #pragma unroll
        for (int i=0; i<7; i++){
            int m = wg + 8*i;
            if (m < Mm){
                outp[m*Dd + d] = mv[i];
                float we = wv[i] * e_d;
                mv[i] = fmaf(wv[i], a_d, fmaf(-we, mv[i], mv[i]));
            }
        }

        e_d = e_n; a_d = a_n;
        #pragma unroll
        for (int i=0; i<7; i++) wv[i] = wn[i];
    }

    // final state at time index T
    float* outp = out_Mv + ((size_t)(b*(Tt+1) + Tt) * Mm) * Dd;
    #pragma unroll
    for (int i=0; i<7; i++){
        int m = wg + 8*i;
        if (m < Mm) outp[m*Dd + d] = mv[i];
    }
}

// ---------------- K3: f = tanh([read,k] @ fW^T + fb), p = sigmoid(f . pW + pb) ----------------
__global__ __launch_bounds__(128) void k3_head(
    const float* __restrict__ f_b, const float* __restrict__ p_W,
    const float* __restrict__ p_b, float* __restrict__ out_p)
{
    const int tid  = threadIdx.x;
    const int lane = tid & 31;
    const int wid  = tid >> 5;
    const int row0 = blockIdx.x * 4;

    __shared__ float cat_s[4][2*Dd];
    __shared__ float sred[4][Dd];

    #pragma unroll
    for (int rr=0; rr<4; rr++){
        int row = row0 + rr;
        cat_s[rr][tid]      = g_read[row*Dd + tid];
        cat_s[rr][Dd + tid] = g_k[row*Dd + tid];
    }
    __syncthreads();

    float a0=0.f,a1=0.f,a2=0.f,a3=0.f;
    #pragma unroll 4
    for (int dd=0; dd<2*Dd; dd++){
        float fw = g_fWt[dd*Dd + tid];
        a0 = fmaf(fw, cat_s[0][dd], a0);
        a1 = fmaf(fw, cat_s[1][dd], a1);
        a2 = fmaf(fw, cat_s[2][dd], a2);
        a3 = fmaf(fw, cat_s[3][dd], a3);
    }
    float fb = f_b[tid], pw = p_W[tid];
    sred[0][tid] = pw * tanhf(a0 + fb);
    sred[1][tid] = pw * tanhf(a1 + fb);
    sred[2][tid] = pw * tanhf(a2 + fb);
    sred[3][tid] = pw * tanhf(a3 + fb);
    __syncthreads();

    // warp wid reduces row wid over 128 channels
    float s = sred[wid][lane] + sred[wid][lane+32] + sred[wid][lane+64] + sred[wid][lane+96];
    #pragma unroll
    for (int o=16; o; o>>=1) s += __shfl_xor_sync(0xffffffffu, s, o);
    if (lane == 0) out_p[row0 + wid] = sigmoidf_(s + p_b[0]);
}

// ---------------- launch ----------------
extern "C" void kernel_launch(void* const* d_in, const int* in_sizes, int n_in,
                              void* d_out, int out_size)
{
    const int*   q       = (const int*)  d_in[0];
    const int*   r       = (const int*)  d_in[1];
    const int*   pid     = (const int*)  d_in[2];
    const float* pid_emb = (const float*)d_in[3];
    const float* k_emb   = (const float*)d_in[4];
    const float* v_emb   = (const float*)d_in[5];
    const float* Mk      = (const float*)d_in[6];
    const float* Mv0     = (const float*)d_in[7];
    const float* f_W     = (const float*)d_in[8];
    const float* f_b     = (const float*)d_in[9];
    const float* p_W     = (const float*)d_in[10];
    const float* p_b     = (const float*)d_in[11];
    const float* e_W     = (const float*)d_in[12];
    const float* e_b     = (const float*)d_in[13];
    const float* a_W     = (const float*)d_in[14];
    const float* a_b     = (const float*)d_in[15];

    float* out_p  = (float*)d_out;              // (64, 200)
    float* out_Mv = (float*)d_out + BT;         // (64, 201, 50, 128)

    k0_transpose<<<256, 256>>>(Mk, e_W, a_W, f_W);
    k1_gates<<<BT/4, 128>>>(q, r, pid, pid_emb, k_emb, v_emb, e_b, a_b);
    {
        dim3 grid(4, Bb);
        k2_scan<<<grid, 256>>>(Mv0, out_Mv);
    }
    k3_head<<<BT/4, 128>>>(f_b, p_W, p_b, out_p);
}